// round 3
// baseline (speedup 1.0000x reference)
#include <cuda_runtime.h>
#include <math.h>

#define NN 8192
#define LL 512
#define KK 30

typedef unsigned long long ull;

// ---------------- packed f32x2 helpers (sm_103a FFMA2) ----------------
__device__ __forceinline__ ull pk2(float a, float b) {
    ull r; asm("mov.b64 %0, {%1,%2};" : "=l"(r) : "f"(a), "f"(b)); return r;
}
__device__ __forceinline__ void upk2(ull v, float& a, float& b) {
    asm("mov.b64 {%0,%1}, %2;" : "=f"(a), "=f"(b) : "l"(v));
}
__device__ __forceinline__ ull fma2(ull x, ull y, ull a) {
    ull r; asm("fma.rn.f32x2 %0, %1, %2, %3;" : "=l"(r) : "l"(x), "l"(y), "l"(a));
    return r;
}

// ---------------- device scratch ----------------
__device__ int   g_knn [NN * KK];
__device__ float g_dist[NN * KK];
__device__ float g_Psrc[NN * 128];
__device__ float g_Ptgt[NN * 128];
__device__ float g_Vnode[NN * 256];
__device__ float g_posA[1023 * 128];
__device__ float g_woT[32 * 64];    // Wo transposed [o][cc]
__device__ float g_w2T[32 * 32];    // W2 transposed [o][j]

// ================= prep kernel: knn | posA | node | transpose =================
__global__ void k_prep(const float* __restrict__ trans,
                       const float* __restrict__ rots,
                       const float* __restrict__ node_emb,
                       const unsigned char* __restrict__ xm,
                       const unsigned char* __restrict__ nm,
                       const float* __restrict__ Wa,
                       const float* __restrict__ Wv,
                       const float* __restrict__ Wo,
                       const float* __restrict__ W2)
{
    __shared__ float sx[LL], sy[LL], sz[LL];
    __shared__ float semb[8][4][36];
    __shared__ float trig[16];
    __shared__ int   s_u8;
    int bid = blockIdx.x, t = threadIdx.x;

    if (bid < 2048) {
        // ---------- kNN: 4 targets / block, warp per target ----------
        int g0 = bid * 4;
        int base = (g0 >> 9) << 9;
        for (int i = t; i < LL; i += 128) {
            const float* p = trans + (size_t)(base + i) * 3;
            sx[i] = p[0]; sy[i] = p[1]; sz[i] = p[2];
        }
        __syncthreads();
        int warp = t >> 5, lane = t & 31;
        int tgt = g0 + warp;
        int tl = tgt & 511;
        float px = sx[tl], py = sy[tl], pz = sz[tl];
        float d[16];
#pragma unroll
        for (int q = 0; q < 16; q++) {
            int c = lane + (q << 5);
            float dx = sx[c] - px, dy = sy[c] - py, dz = sz[c] - pz;
            float d2 = dx * dx + dy * dy + dz * dz;
            d[q] = (c == tl) ? 1e30f : d2;
        }
        for (int it = 0; it < KK; it++) {
            float bv = d[0]; int bq = 0;
#pragma unroll
            for (int q = 1; q < 16; q++)
                if (d[q] < bv) { bv = d[q]; bq = q; }
            int bi = lane + (bq << 5);
#pragma unroll
            for (int off = 16; off > 0; off >>= 1) {
                float ov = __shfl_down_sync(0xffffffffu, bv, off);
                int   oi = __shfl_down_sync(0xffffffffu, bi, off);
                if (ov < bv || (ov == bv && oi < bi)) { bv = ov; bi = oi; }
            }
            bv = __shfl_sync(0xffffffffu, bv, 0);
            bi = __shfl_sync(0xffffffffu, bi, 0);
            if (lane == (bi & 31)) {
                int wq = bi >> 5;
#pragma unroll
                for (int q = 0; q < 16; q++)
                    if (q == wq) d[q] = 1e30f;
            }
            if (lane == 0) {
                g_knn [tgt * KK + it] = base + bi;
                g_dist[tgt * KK + it] = sqrtf(bv);
            }
        }
    } else if (bid < 2048 + 1023) {
        // ---------- posA table ----------
        int dd = bid - 2048;
        float delta = (float)(dd - 511);
        if (t < 8) {
            float freq = expf(-(float)(2 * t) * (9.210340371976184f / 16.0f));
            float ang = delta * freq;
            trig[t]     = cosf(ang);
            trig[8 + t] = sinf(ang);
        }
        __syncthreads();
        float s = 0.f;
#pragma unroll
        for (int j = 0; j < 8; j++) {
            s = fmaf(trig[j],     Wa[(86 + j) * 128 + t], s);
            s = fmaf(trig[8 + j], Wa[(94 + j) * 128 + t], s);
        }
        g_posA[dd * 128 + t] = s;
    } else if (bid < 2048 + 1023 + 1024) {
        // ---------- node precompute: 8 nodes / block ----------
        int n0 = (bid - (2048 + 1023)) * 8;
        // mask layout probe (int32 0/1 has zero bytes at idx%4!=0)
        if (t < 64) {
            int any = 0;
#pragma unroll
            for (int j = 1; j < 4; j++) any |= (int)xm[4 * t + j];
            unsigned b = __ballot_sync(0xffffffffu, any != 0);
            if (t == 0) s_u8 = (b != 0u) ? 1 : 0;
        }
        __syncthreads();
        int u8 = s_u8;
        for (int m = 0; m < 8; m++) {
            int n = n0 + m;
            int r = t >> 5, c = t & 31;
            semb[m][r][c] = node_emb[n * 128 + t];
            if (t == 0) {
                const float* R = rots + n * 9;
                const float bx0 = -0.525f, by0 = 1.363f, bx2 = 1.526f;
#pragma unroll
                for (int i = 0; i < 3; i++) {
                    float r0 = R[i * 3 + 0], r1 = R[i * 3 + 1];
                    semb[m][1 + i][32 + 0] = r0 * bx0 + r1 * by0;
                    semb[m][1 + i][32 + 1] = 0.f;
                    semb[m][1 + i][32 + 2] = r0 * bx2;
                }
                int xv = u8 ? (int)xm[n] : (int)xm[n * 4];
                int nv = u8 ? (int)nm[n] : (int)nm[n * 4];
                semb[m][0][32] = 0.f;
                semb[m][0][33] = 0.f;
                semb[m][0][34] = (nv && !xv) ? 1.f : 0.f;
            }
        }
        __syncthreads();
        // Psrc/Ptgt packed: acc2[m] = {S,T}
        ull acc2[8];
#pragma unroll
        for (int m = 0; m < 8; m++) acc2[m] = 0ull;
        for (int ch = 0; ch < 35; ch++) {
            ull w2 = pk2(Wa[ch * 128 + t], Wa[(35 + ch) * 128 + t]);
#pragma unroll
            for (int m = 0; m < 8; m++) {
                float e0 = semb[m][0][ch];
                acc2[m] = fma2(pk2(e0, e0), w2, acc2[m]);
            }
        }
#pragma unroll
        for (int m = 0; m < 8; m++) {
            float s, tt; upk2(acc2[m], s, tt);
            g_Psrc[(n0 + m) * 128 + t] = s;
            g_Ptgt[(n0 + m) * 128 + t] = tt;
        }
        // Vnode: rows (r0, r0+2) packed
        int c = t & 63, r0 = t >> 6;
        ull v2[8];
#pragma unroll
        for (int m = 0; m < 8; m++) v2[m] = 0ull;
        for (int ch = 0; ch < 35; ch++) {
            float w = Wv[ch * 64 + c];
            ull wd = pk2(w, w);
#pragma unroll
            for (int m = 0; m < 8; m++)
                v2[m] = fma2(pk2(semb[m][r0][ch], semb[m][r0 + 2][ch]), wd, v2[m]);
        }
#pragma unroll
        for (int m = 0; m < 8; m++) {
            float a, b; upk2(v2[m], a, b);
            g_Vnode[(n0 + m) * 256 + t]       = a;
            g_Vnode[(n0 + m) * 256 + 128 + t] = b;
        }
    } else {
        // ---------- weight transposes ----------
        for (int idx = t; idx < 2048; idx += 128) {
            int o = idx & 31, cc = idx >> 5;
            g_woT[o * 64 + cc] = Wo[idx];
        }
        for (int idx = t; idx < 1024; idx += 128) {
            int o = idx & 31, j = idx >> 5;
            g_w2T[o * 32 + j] = W2[idx];
        }
    }
}

// ================= main kernel: one block per target node =================
__global__ void __launch_bounds__(128)
k_main(const float* __restrict__ Wa,
       const float* __restrict__ avec,
       const float* __restrict__ Wg,
       float* __restrict__ out)
{
    __shared__ __align__(16) float s_rbf[KK][16];
    __shared__ __align__(16) float s_base[KK][128];
    __shared__ __align__(16) float s_part[2][256];
    __shared__ __align__(16) float s_agg[256];
    __shared__ float s_logit[KK][8];
    __shared__ float s_alpha[KK][8];
    __shared__ float s_y[128];
    __shared__ float s_yg[128];
    __shared__ float s_gate[32];
    __shared__ int   s_src[KK];
    __shared__ float s_dist[KK];
    __shared__ float s_valid[KK];

    int n = blockIdx.x, t = threadIdx.x;
    int w = t >> 5, l = t & 31;

    if (t < KK) {
        int s = g_knn[n * KK + t];
        float d = g_dist[n * KK + t];
        s_src[t] = s;
        s_dist[t] = d;
        s_valid[t] = (isfinite(d) && d > 1e-3f) ? 1.f : 0.f;
    }
    // RBF dot weights (rows 70..85 of W_alpha), packed in j-pairs
    ull arbp[8];
#pragma unroll
    for (int jj = 0; jj < 8; jj++)
        arbp[jj] = pk2(Wa[(70 + 2 * jj) * 128 + t], Wa[(71 + 2 * jj) * 128 + t]);
    float ptgt = g_Ptgt[n * 128 + t];
    __syncthreads();

    // ---- RBF features ----
    for (int i = t; i < KK * 16; i += 128) {
        int e = i >> 4, j = i & 15;
        float x = (s_dist[e] - (float)j * (20.0f / 15.0f)) * 0.8f;
        s_rbf[e][j] = __expf(-x * x);
    }
    __syncthreads();

    // ---- phase B: base[e][c] = ptgt[c] + rbf[e] . arb[:,c]  (channel layout) ----
    for (int e = 0; e < KK; e++) {
        ull acc = pk2(ptgt, 0.f);
        const ulonglong2* rp = reinterpret_cast<const ulonglong2*>(&s_rbf[e][0]);
#pragma unroll
        for (int jj = 0; jj < 4; jj++) {
            ulonglong2 r2 = rp[jj];
            acc = fma2(r2.x, arbp[2 * jj], acc);
            acc = fma2(r2.y, arbp[2 * jj + 1], acc);
        }
        float a, b; upk2(acc, a, b);
        s_base[e][t] = a + b;
    }
    __syncthreads();

    // ---- phase C: logits, warp-per-edge, float4 gathers ----
    {
        float4 av4 = *reinterpret_cast<const float4*>(avec + 4 * l);
        for (int e = w; e < KK; e += 4) {
            int src = s_src[e];
            float4 b4 = *reinterpret_cast<const float4*>(&s_base[e][4 * l]);
            float4 p4 = *reinterpret_cast<const float4*>(g_Psrc + (size_t)src * 128 + 4 * l);
            float4 q4 = *reinterpret_cast<const float4*>(g_posA + (size_t)(src - n + 511) * 128 + 4 * l);
            float x0 = b4.x + p4.x + q4.x;
            float x1 = b4.y + p4.y + q4.y;
            float x2 = b4.z + p4.z + q4.z;
            float x3 = b4.w + p4.w + q4.w;
            float h0 = x0 / (1.f + __expf(-x0));
            float h1 = x1 / (1.f + __expf(-x1));
            float h2 = x2 / (1.f + __expf(-x2));
            float h3 = x3 / (1.f + __expf(-x3));
            float p = h0 * av4.x + h1 * av4.y + h2 * av4.z + h3 * av4.w;
            p += __shfl_xor_sync(0xffffffffu, p, 1);
            p += __shfl_xor_sync(0xffffffffu, p, 2);
            if ((l & 3) == 0) {
                float lg = (p > 0.f) ? p : 0.2f * p;
                s_logit[e][l >> 2] = (s_valid[e] > 0.f) ? lg : -1e9f;
            }
        }
    }
    __syncthreads();

    // ---- phase D: per-head softmax over 30 edges (warp 0) ----
    if (t < 32) {
        int h = t >> 2, q = t & 3;
        float mx = -1e30f;
        for (int e = q; e < KK; e += 4) mx = fmaxf(mx, s_logit[e][h]);
        mx = fmaxf(mx, __shfl_xor_sync(0xffffffffu, mx, 1));
        mx = fmaxf(mx, __shfl_xor_sync(0xffffffffu, mx, 2));
        float den = 0.f;
        for (int e = q; e < KK; e += 4) {
            float ex = __expf(s_logit[e][h] - mx) * s_valid[e];
            s_alpha[e][h] = ex; den += ex;
        }
        den += __shfl_xor_sync(0xffffffffu, den, 1);
        den += __shfl_xor_sync(0xffffffffu, den, 2);
        float inv = 1.f / (den + 1e-9f);
        for (int e = q; e < KK; e += 4) s_alpha[e][h] *= inv;
    }
    __syncthreads();

    // ---- phase E: weighted value gather (float4 + FMA2) ----
    {
        int g = t >> 6, l64 = t & 63;
        int off = 4 * l64;
        int head = (off & 63) >> 3;
        ull accA = 0ull, accB = 0ull;
        for (int e = g; e < KK; e += 2) {
            int src = s_src[e];
            float al = s_alpha[e][head];
            ull ad = pk2(al, al);
            ulonglong2 v = *reinterpret_cast<const ulonglong2*>(g_Vnode + (size_t)src * 256 + off);
            accA = fma2(v.x, ad, accA);
            accB = fma2(v.y, ad, accB);
        }
        float4 r;
        upk2(accA, r.x, r.y);
        upk2(accB, r.z, r.w);
        *reinterpret_cast<float4*>(&s_part[g][off]) = r;
    }
    __syncthreads();
    s_agg[t]       = s_part[0][t]       + s_part[1][t];
    s_agg[t + 128] = s_part[0][t + 128] + s_part[1][t + 128];
    __syncthreads();

    // ---- phase F: y = agg @ Wo ; gate ; out ----
    int r = t >> 5, o = t & 31;
    {
        ull acc = 0ull;
        const ull* ap = reinterpret_cast<const ull*>(&s_agg[r * 64]);
        const ull* wp = reinterpret_cast<const ull*>(&g_woT[o * 64]);
#pragma unroll
        for (int k = 0; k < 32; k++) acc = fma2(ap[k], wp[k], acc);
        float a, b; upk2(acc, a, b);
        s_y[t] = a + b;
    }
    __syncthreads();
    if (t < 32) {
        float g = 0.f;
#pragma unroll
        for (int j = 0; j < 32; j++) g = fmaf(s_y[j], Wg[j * 32 + t], g);
        s_gate[t] = g / (1.f + __expf(-g));
    }
    __syncthreads();
    s_yg[t] = s_y[t] * s_gate[o];
    __syncthreads();
    {
        ull acc = 0ull;
        const ull* yp = reinterpret_cast<const ull*>(&s_yg[r * 32]);
        const ull* wp = reinterpret_cast<const ull*>(&g_w2T[o * 32]);
#pragma unroll
        for (int k = 0; k < 16; k++) acc = fma2(yp[k], wp[k], acc);
        float a, b; upk2(acc, a, b);
        out[n * 128 + t] = a + b;
    }
}

// ---------------- launch ----------------
extern "C" void kernel_launch(void* const* d_in, const int* in_sizes, int n_in,
                              void* d_out, int out_size)
{
    const float* rots     = (const float*)d_in[0];
    const float* trans    = (const float*)d_in[1];
    const float* node_emb = (const float*)d_in[2];
    const unsigned char* xm = (const unsigned char*)d_in[4];
    const unsigned char* nm = (const unsigned char*)d_in[5];
    const float* Wa = (const float*)d_in[6];
    const float* av = (const float*)d_in[7];
    const float* Wv = (const float*)d_in[8];
    const float* Wo = (const float*)d_in[9];
    const float* Wg = (const float*)d_in[10];
    const float* W2 = (const float*)d_in[11];
    float* out = (float*)d_out;

    k_prep<<<4096, 128>>>(trans, rots, node_emb, xm, nm, Wa, Wv, Wo, W2);
    k_main<<<NN, 128>>>(Wa, av, Wg, out);
}